// round 7
// baseline (speedup 1.0000x reference)
#include <cuda_runtime.h>
#include <cuda_bf16.h>
#include <mma.h>

using namespace nvcuda;

#define BB    64
#define TXX   1024
#define AD    1024
#define UN    1024
#define VOC   32000
#define ED    512
#define KXIN  2560
#define NZ    4096
#define ZSPLITS 4

#define APITCH 40     // A smem pitch (bf16): 32 + 8, 80 B rows
#define BPITCH 72     // B smem pitch (bf16): 64 + 8, 144 B rows
#define STAGE_ELEMS 9728   // (64*40)*2 + (32*72)*2 bf16 elems = 19456 B

// ---------------- scratch (__device__ globals; NEVER passed from host) ----------------
__device__ __align__(16) float g_pctx[8 * BB * AD];
__device__ __align__(16) __nv_bfloat16 g_xz_hi[BB * KXIN];
__device__ __align__(16) __nv_bfloat16 g_xz_lo[BB * KXIN];
__device__ __align__(16) __nv_bfloat16 g_xv_hi[BB * UN];
__device__ __align__(16) __nv_bfloat16 g_xv_lo[BB * UN];
__device__ __align__(16) float g_zpart[ZSPLITS * BB * NZ];
__device__ __align__(16) float g_logits[BB * VOC];

__device__ __forceinline__ float sigf(float x) { return 1.0f / (1.0f + __expf(-x)); }

__device__ __forceinline__ void split_write(__nv_bfloat16* hi, __nv_bfloat16* lo,
                                            size_t idx, float v) {
    __nv_bfloat16 h = __float2bfloat16(v);
    hi[idx] = h;
    lo[idx] = __float2bfloat16(v - __bfloat162float(h));
}

// ---------------- K1: context partial sums ----------------
__global__ void ctx_partial(const float* __restrict__ a) {
    int d4 = threadIdx.x;                 // 0..255 (float4 lanes)
    int b  = blockIdx.y;
    int t0 = blockIdx.x * 128;
    const float4* p = (const float4*)(a + ((size_t)b * TXX + t0) * AD) + d4;
    float4 s = make_float4(0.f, 0.f, 0.f, 0.f);
#pragma unroll 8
    for (int t = 0; t < 128; t++) {
        float4 v = p[(size_t)t * 256];
        s.x += v.x; s.y += v.y; s.z += v.z; s.w += v.w;
    }
    ((float4*)g_pctx)[((size_t)blockIdx.x * BB + b) * 256 + d4] = s;
}

// ---------------- K2: finalize ctx + build xin bf16 hi/lo images ----------------
__global__ void ctx_finalize(const int* __restrict__ X, const float* __restrict__ emb,
                             const float* __restrict__ h,
                             float* __restrict__ o_ctx, float* __restrict__ o_alpha) {
    int b = blockIdx.y;
    int d = blockIdx.x * 256 + threadIdx.x;
    float s = 0.f;
#pragma unroll
    for (int j = 0; j < 8; j++) s += g_pctx[((size_t)j * BB + b) * AD + d];
    o_ctx[b * AD + d]    = s;
    o_alpha[b * TXX + d] = 1.0f;
    size_t row = (size_t)b * KXIN;
    split_write(g_xz_hi, g_xz_lo, row + d, s);                     // k [0,1024)
    if (d < ED) {
        int tok = X[b];
        split_write(g_xz_hi, g_xz_lo, row + AD + d, emb[(size_t)tok * ED + d]);
    }
    split_write(g_xz_hi, g_xz_lo, row + AD + ED + d, h[b * UN + d]);
}

// ---------------- wmma GEMM: out[64,...] = x[64,K] @ W[K,N]  (bf16 hi/lo split) ----------------
// 128 thr = 4 warps; tile 64m x 64n; 2-stage pipeline of K=32 stages;
// static smem 38912 B; ONE __syncthreads per stage; A+B reg-prefetched.
__global__ void __launch_bounds__(128, 4)
wgemm(const float* __restrict__ Wa, const float* __restrict__ Wb, int kbound, int ldw,
      int in_sel, int ldx, int nstages, int out_sel, int ldo) {
    __shared__ __align__(32) __nv_bfloat16 sm[2 * STAGE_ELEMS];

    const __nv_bfloat16* xhi = in_sel ? g_xv_hi : g_xz_hi;
    const __nv_bfloat16* xlo = in_sel ? g_xv_lo : g_xz_lo;

    int tid = threadIdx.x, w = tid >> 5;
    int n0 = blockIdx.x * 64;
    int k0 = blockIdx.y * nstages * 32;
    float* out = out_sel ? g_logits : (g_zpart + (size_t)blockIdx.y * BB * NZ);

    wmma::fragment<wmma::accumulator, 16, 16, 16, float> acc[4];
#pragma unroll
    for (int i = 0; i < 4; i++) wmma::fill_fragment(acc[i], 0.0f);

    // per-thread prefetch: A = 4 uint4 (2 hi + 2 lo), B = 4 float4
    uint4  pa[4];
    float4 pb[4];
    auto ldAB = [&](int s) {
        int kg0 = k0 + s * 32;
        // A: 64 rows x 32 k, hi/lo. hi: 256 uint4, lo: 256 uint4.
#pragma unroll
        for (int i = 0; i < 2; i++) {
            int idx = tid + i * 128;            // [0,256)
            int row = idx >> 2, j = idx & 3;
            size_t so = ((size_t)row * ldx + kg0) / 8 + j;
            pa[i]     = ((const uint4*)xhi)[so];
            pa[i + 2] = ((const uint4*)xlo)[so];
        }
        // B: 32 k x 64 n fp32 = 512 float4
#pragma unroll
        for (int i = 0; i < 4; i++) {
            int idx = tid + i * 128;
            int k = idx >> 4, f4c = idx & 15;
            int kg = kg0 + k;
            const float* wrow = (kg < kbound) ? (Wa + (size_t)kg * ldw)
                                              : (Wb + (size_t)(kg - kbound) * ldw);
            pb[i] = __ldg((const float4*)(wrow + n0) + f4c);
        }
    };

    ldAB(0);
    for (int s = 0; s < nstages; s++) {
        __nv_bfloat16* stg = sm + (s & 1) * STAGE_ELEMS;
        __nv_bfloat16* Ah = stg;
        __nv_bfloat16* Al = stg + 2560;
        __nv_bfloat16* Bh = stg + 5120;
        __nv_bfloat16* Bl = stg + 7424;
        // --- store stage s from prefetch regs ---
#pragma unroll
        for (int i = 0; i < 2; i++) {
            int idx = tid + i * 128;
            int row = idx >> 2, j = idx & 3;
            ((uint4*)Ah)[row * 5 + j] = pa[i];
            ((uint4*)Al)[row * 5 + j] = pa[i + 2];
        }
#pragma unroll
        for (int i = 0; i < 4; i++) {
            int idx = tid + i * 128;
            int k = idx >> 4, f4c = idx & 15;
            float4 v = pb[i];
            __nv_bfloat16 h0 = __float2bfloat16(v.x), h1 = __float2bfloat16(v.y);
            __nv_bfloat16 h2 = __float2bfloat16(v.z), h3 = __float2bfloat16(v.w);
            __nv_bfloat16 l0 = __float2bfloat16(v.x - __bfloat162float(h0));
            __nv_bfloat16 l1 = __float2bfloat16(v.y - __bfloat162float(h1));
            __nv_bfloat16 l2 = __float2bfloat16(v.z - __bfloat162float(h2));
            __nv_bfloat16 l3 = __float2bfloat16(v.w - __bfloat162float(h3));
            int bo = k * BPITCH + f4c * 4;
            *(__nv_bfloat162*)(Bh + bo)     = __halves2bfloat162(h0, h1);
            *(__nv_bfloat162*)(Bh + bo + 2) = __halves2bfloat162(h2, h3);
            *(__nv_bfloat162*)(Bl + bo)     = __halves2bfloat162(l0, l1);
            *(__nv_bfloat162*)(Bl + bo + 2) = __halves2bfloat162(l2, l3);
        }
        __syncthreads();
        if (s + 1 < nstages) ldAB(s + 1);      // LDGs fly under the mma below
        // --- compute: warp w owns n-strip [w*16, w*16+16) ---
#pragma unroll
        for (int kt = 0; kt < 2; kt++) {
            wmma::fragment<wmma::matrix_b, 16, 16, 16, __nv_bfloat16, wmma::row_major> bh, bl;
            wmma::load_matrix_sync(bh, Bh + kt * 16 * BPITCH + w * 16, BPITCH);
            wmma::load_matrix_sync(bl, Bl + kt * 16 * BPITCH + w * 16, BPITCH);
            wmma::fragment<wmma::matrix_a, 16, 16, 16, __nv_bfloat16, wmma::row_major> af[4];
#pragma unroll
            for (int mt = 0; mt < 4; mt++)
                wmma::load_matrix_sync(af[mt], Ah + mt * 16 * APITCH + kt * 16, APITCH);
#pragma unroll
            for (int mt = 0; mt < 4; mt++) wmma::mma_sync(acc[mt], af[mt], bh, acc[mt]);
#pragma unroll
            for (int mt = 0; mt < 4; mt++) wmma::mma_sync(acc[mt], af[mt], bl, acc[mt]);
#pragma unroll
            for (int mt = 0; mt < 4; mt++)
                wmma::load_matrix_sync(af[mt], Al + mt * 16 * APITCH + kt * 16, APITCH);
#pragma unroll
            for (int mt = 0; mt < 4; mt++) wmma::mma_sync(acc[mt], af[mt], bh, acc[mt]);
        }
    }
#pragma unroll
    for (int mt = 0; mt < 4; mt++)
        wmma::store_matrix_sync(out + (size_t)(mt * 16) * ldo + n0 + w * 16,
                                acc[mt], ldo, wmma::mem_row_major);
}

// ---------------- K4: LSTM gates + h_new bf16 images ----------------
__global__ void gates(const float* __restrict__ c, const float* __restrict__ bl,
                      float* __restrict__ o_h, float* __restrict__ o_c) {
    int b = blockIdx.y;
    int u = blockIdx.x * 256 + threadIdx.x;
    float zi = bl[u], zf = bl[u + UN], zg = bl[u + 2 * UN], zo = bl[u + 3 * UN];
#pragma unroll
    for (int s = 0; s < ZSPLITS; s++) {
        const float* zp = g_zpart + (size_t)s * BB * NZ + (size_t)b * NZ;
        zi += zp[u]; zf += zp[u + UN]; zg += zp[u + 2 * UN]; zo += zp[u + 3 * UN];
    }
    float cn = sigf(zf) * c[b * UN + u] + sigf(zi) * tanhf(zg);
    float hn = sigf(zo) * tanhf(cn);
    o_c[b * UN + u] = cn;
    o_h[b * UN + u] = hn;
    split_write(g_xv_hi, g_xv_lo, (size_t)b * UN + u, hn);
}

// ---------------- K6: softmax over vocab (float4) ----------------
__global__ void softmax_k(const float* __restrict__ bv, float* __restrict__ o_y) {
    int b = blockIdx.x, tid = threadIdx.x;
    __shared__ float red[1024];
    const float4* lg4 = (const float4*)(g_logits + (size_t)b * VOC);
    const float4* bv4 = (const float4*)bv;
    float4* oy4 = (float4*)(o_y + (size_t)b * VOC);
    float mx = -1e30f;
    for (int n = tid; n < VOC / 4; n += 1024) {
        float4 l = lg4[n], v = bv4[n];
        mx = fmaxf(mx, fmaxf(fmaxf(l.x + v.x, l.y + v.y), fmaxf(l.z + v.z, l.w + v.w)));
    }
    red[tid] = mx; __syncthreads();
    for (int s = 512; s > 0; s >>= 1) {
        if (tid < s) red[tid] = fmaxf(red[tid], red[tid + s]);
        __syncthreads();
    }
    float M = red[0]; __syncthreads();
    float sum = 0.f;
    for (int n = tid; n < VOC / 4; n += 1024) {
        float4 l = lg4[n], v = bv4[n];
        float4 e = make_float4(__expf(l.x + v.x - M), __expf(l.y + v.y - M),
                               __expf(l.z + v.z - M), __expf(l.w + v.w - M));
        oy4[n] = e;
        sum += e.x + e.y + e.z + e.w;
    }
    red[tid] = sum; __syncthreads();
    for (int s = 512; s > 0; s >>= 1) {
        if (tid < s) red[tid] += red[tid + s];
        __syncthreads();
    }
    float inv = 1.0f / red[0];
    for (int n = tid; n < VOC / 4; n += 1024) {
        float4 e = oy4[n];
        e.x *= inv; e.y *= inv; e.z *= inv; e.w *= inv;
        oy4[n] = e;
    }
}

// ---------------- launch ----------------
extern "C" void kernel_launch(void* const* d_in, const int* in_sizes, int n_in,
                              void* d_out, int out_size) {
    (void)in_sizes; (void)n_in; (void)out_size;
    const int*   X   = (const int*)d_in[0];
    const float* a   = (const float*)d_in[1];
    const float* h   = (const float*)d_in[2];
    const float* c   = (const float*)d_in[3];
    const float* emb = (const float*)d_in[4];
    // d_in[5..10] dead (softmax over size-1 axis == 1)
    const float* Wx  = (const float*)d_in[11];
    const float* Wh  = (const float*)d_in[12];
    const float* bl  = (const float*)d_in[13];
    const float* Wv  = (const float*)d_in[14];
    const float* bv  = (const float*)d_in[15];

    float* out     = (float*)d_out;
    float* o_y     = out;
    float* o_ctx   = o_y + (size_t)BB * VOC;
    float* o_alpha = o_ctx + BB * AD;
    float* o_h     = o_alpha + BB * TXX;
    float* o_c     = o_h + BB * UN;

    ctx_partial<<<dim3(8, 64), 256>>>(a);
    ctx_finalize<<<dim3(4, 64), 256>>>(X, emb, h, o_ctx, o_alpha);
    // z = xin@[Wx;Wh] : K=2560 = 4 splits x 20 stages of 32; 64 n-blocks
    wgemm<<<dim3(NZ / 64, ZSPLITS), 128>>>(
        Wx, Wh, AD + ED, NZ, /*in_sel=*/0, KXIN, (KXIN / 32) / ZSPLITS, /*out_sel=*/0, NZ);
    gates<<<dim3(4, 64), 256>>>(c, bl, o_h, o_c);
    // logits = h_new@Wv : K=1024 = 32 stages of 32; 500 n-blocks
    wgemm<<<dim3(VOC / 64, 1), 128>>>(
        Wv, Wv, 0x7fffffff, VOC, /*in_sel=*/1, UN, UN / 32, /*out_sel=*/1, VOC);
    softmax_k<<<64, 1024>>>(bv, o_y);
}

// round 8
// speedup vs baseline: 1.0116x; 1.0116x over previous
#include <cuda_runtime.h>
#include <cuda_bf16.h>
#include <mma.h>

using namespace nvcuda;

#define BB    64
#define TXX   1024
#define AD    1024
#define UN    1024
#define VOC   32000
#define ED    512
#define KXIN  2560
#define NZ    4096
#define ZSPLITS 4

#define APITCH 72       // A smem pitch (bf16): 64+8
#define BPITCH 136      // B smem pitch (bf16): 128+8
// stage: Ah 64*72 + Al 64*72 + Bh 64*136 + Bl 64*136 = 26624 bf16 = 53248 B
#define A_ELEMS   4608
#define B_ELEMS   8704
#define STAGE_ELEMS 26624
#define WG_SMEM  (2 * STAGE_ELEMS * 2)   // 106496 B

// ---------------- scratch (__device__ globals; NEVER passed from host) ----------------
__device__ __align__(16) float g_pctx[8 * BB * AD];
__device__ __align__(16) __nv_bfloat16 g_xz_hi[BB * KXIN];
__device__ __align__(16) __nv_bfloat16 g_xz_lo[BB * KXIN];
__device__ __align__(16) __nv_bfloat16 g_xv_hi[BB * UN];
__device__ __align__(16) __nv_bfloat16 g_xv_lo[BB * UN];
__device__ __align__(16) float g_zpart[ZSPLITS * BB * NZ];
__device__ __align__(16) float g_logits[BB * VOC];

__device__ __forceinline__ float sigf(float x) { return 1.0f / (1.0f + __expf(-x)); }

__device__ __forceinline__ void split_write(__nv_bfloat16* hi, __nv_bfloat16* lo,
                                            size_t idx, float v) {
    __nv_bfloat16 h = __float2bfloat16(v);
    hi[idx] = h;
    lo[idx] = __float2bfloat16(v - __bfloat162float(h));
}

// ---------------- K1: context partial sums ----------------
__global__ void ctx_partial(const float* __restrict__ a) {
    int d4 = threadIdx.x;
    int b  = blockIdx.y;
    int t0 = blockIdx.x * 128;
    const float4* p = (const float4*)(a + ((size_t)b * TXX + t0) * AD) + d4;
    float4 s = make_float4(0.f, 0.f, 0.f, 0.f);
#pragma unroll 8
    for (int t = 0; t < 128; t++) {
        float4 v = p[(size_t)t * 256];
        s.x += v.x; s.y += v.y; s.z += v.z; s.w += v.w;
    }
    ((float4*)g_pctx)[((size_t)blockIdx.x * BB + b) * 256 + d4] = s;
}

// ---------------- K2: finalize ctx + build xin bf16 hi/lo images ----------------
__global__ void ctx_finalize(const int* __restrict__ X, const float* __restrict__ emb,
                             const float* __restrict__ h,
                             float* __restrict__ o_ctx, float* __restrict__ o_alpha) {
    int b = blockIdx.y;
    int d = blockIdx.x * 256 + threadIdx.x;
    float s = 0.f;
#pragma unroll
    for (int j = 0; j < 8; j++) s += g_pctx[((size_t)j * BB + b) * AD + d];
    o_ctx[b * AD + d]    = s;
    o_alpha[b * TXX + d] = 1.0f;
    size_t row = (size_t)b * KXIN;
    split_write(g_xz_hi, g_xz_lo, row + d, s);
    if (d < ED) {
        int tok = X[b];
        split_write(g_xz_hi, g_xz_lo, row + AD + d, emb[(size_t)tok * ED + d]);
    }
    split_write(g_xz_hi, g_xz_lo, row + AD + ED + d, h[b * UN + d]);
}

// ---------------- wmma GEMM: out[64,...] = x[64,K] @ W[K,N]  (bf16 hi/lo split) ----------------
// 256 thr = 8 warps; tile 64m x 128n; K=64 stages; full 2-stage smem double
// buffer (106496 B dynamic); ONE __syncthreads per stage; A+B reg-prefetched.
extern __shared__ __nv_bfloat16 dsm[];

__global__ void __launch_bounds__(256, 2)
wgemm(const float* __restrict__ Wa, const float* __restrict__ Wb, int kbound, int ldw,
      int in_sel, int ldx, int nstages, int out_sel, int ldo) {
    const __nv_bfloat16* xhi = in_sel ? g_xv_hi : g_xz_hi;
    const __nv_bfloat16* xlo = in_sel ? g_xv_lo : g_xz_lo;

    int tid = threadIdx.x, w = tid >> 5;
    int n0 = blockIdx.x * 128;
    int k0 = blockIdx.y * nstages * 64;
    float* out = out_sel ? g_logits : (g_zpart + (size_t)blockIdx.y * BB * NZ);

    wmma::fragment<wmma::accumulator, 16, 16, 16, float> acc[4];
#pragma unroll
    for (int i = 0; i < 4; i++) wmma::fill_fragment(acc[i], 0.0f);

    // per-thread prefetch: A = 2 hi + 2 lo uint4, B = 8 float4
    uint4  pa[4];
    float4 pb[8];
    auto ldAB = [&](int s) {
        int kg0 = k0 + s * 64;
        // A: 64 rows x 64 k hi/lo = 512 uint4 each; 256 thr -> 2 each
#pragma unroll
        for (int i = 0; i < 2; i++) {
            int idx = tid + i * 256;
            int row = idx >> 3, j = idx & 7;
            size_t so = ((size_t)row * ldx + kg0) / 8 + j;
            pa[i]     = ((const uint4*)xhi)[so];
            pa[i + 2] = ((const uint4*)xlo)[so];
        }
        // B: 64 k x 128 n fp32 = 2048 float4; 256 thr -> 8 each
#pragma unroll
        for (int i = 0; i < 8; i++) {
            int idx = tid + i * 256;
            int k = idx >> 5, f4c = idx & 31;
            int kg = kg0 + k;
            const float* wrow = (kg < kbound) ? (Wa + (size_t)kg * ldw)
                                              : (Wb + (size_t)(kg - kbound) * ldw);
            pb[i] = __ldg((const float4*)(wrow + n0) + f4c);
        }
    };
    auto stAB = [&](int s) {
        __nv_bfloat16* stg = dsm + (s & 1) * STAGE_ELEMS;
        __nv_bfloat16* Ah = stg;
        __nv_bfloat16* Al = stg + A_ELEMS;
        __nv_bfloat16* Bh = stg + 2 * A_ELEMS;
        __nv_bfloat16* Bl = stg + 2 * A_ELEMS + B_ELEMS;
#pragma unroll
        for (int i = 0; i < 2; i++) {
            int idx = tid + i * 256;
            int row = idx >> 3, j = idx & 7;
            ((uint4*)Ah)[row * 9 + j] = pa[i];
            ((uint4*)Al)[row * 9 + j] = pa[i + 2];
        }
#pragma unroll
        for (int i = 0; i < 8; i++) {
            int idx = tid + i * 256;
            int k = idx >> 5, f4c = idx & 31;
            float4 v = pb[i];
            __nv_bfloat16 h0 = __float2bfloat16(v.x), h1 = __float2bfloat16(v.y);
            __nv_bfloat16 h2 = __float2bfloat16(v.z), h3 = __float2bfloat16(v.w);
            __nv_bfloat16 l0 = __float2bfloat16(v.x - __bfloat162float(h0));
            __nv_bfloat16 l1 = __float2bfloat16(v.y - __bfloat162float(h1));
            __nv_bfloat16 l2 = __float2bfloat16(v.z - __bfloat162float(h2));
            __nv_bfloat16 l3 = __float2bfloat16(v.w - __bfloat162float(h3));
            int bo = k * BPITCH + f4c * 4;
            *(__nv_bfloat162*)(Bh + bo)     = __halves2bfloat162(h0, h1);
            *(__nv_bfloat162*)(Bh + bo + 2) = __halves2bfloat162(h2, h3);
            *(__nv_bfloat162*)(Bl + bo)     = __halves2bfloat162(l0, l1);
            *(__nv_bfloat162*)(Bl + bo + 2) = __halves2bfloat162(l2, l3);
        }
    };

    ldAB(0);
    stAB(0);
    __syncthreads();                 // stage 0 visible

    for (int s = 0; s < nstages; s++) {
        if (s + 1 < nstages) ldAB(s + 1);   // LDGs fly under this stage's mma
        __nv_bfloat16* stg = dsm + (s & 1) * STAGE_ELEMS;
        __nv_bfloat16* Ah = stg;
        __nv_bfloat16* Al = stg + A_ELEMS;
        __nv_bfloat16* Bh = stg + 2 * A_ELEMS;
        __nv_bfloat16* Bl = stg + 2 * A_ELEMS + B_ELEMS;
        // warp w owns n-strip [w*16, w*16+16) of 128
#pragma unroll
        for (int kt = 0; kt < 4; kt++) {
            wmma::fragment<wmma::matrix_b, 16, 16, 16, __nv_bfloat16, wmma::row_major> bh, bl;
            wmma::load_matrix_sync(bh, Bh + kt * 16 * BPITCH + w * 16, BPITCH);
            wmma::load_matrix_sync(bl, Bl + kt * 16 * BPITCH + w * 16, BPITCH);
            wmma::fragment<wmma::matrix_a, 16, 16, 16, __nv_bfloat16, wmma::row_major> af[4];
#pragma unroll
            for (int mt = 0; mt < 4; mt++)
                wmma::load_matrix_sync(af[mt], Ah + mt * 16 * APITCH + kt * 16, APITCH);
#pragma unroll
            for (int mt = 0; mt < 4; mt++) wmma::mma_sync(acc[mt], af[mt], bh, acc[mt]);
#pragma unroll
            for (int mt = 0; mt < 4; mt++) wmma::mma_sync(acc[mt], af[mt], bl, acc[mt]);
#pragma unroll
            for (int mt = 0; mt < 4; mt++)
                wmma::load_matrix_sync(af[mt], Al + mt * 16 * APITCH + kt * 16, APITCH);
#pragma unroll
            for (int mt = 0; mt < 4; mt++) wmma::mma_sync(acc[mt], af[mt], bh, acc[mt]);
        }
        if (s + 1 < nstages) stAB(s + 1);   // write alternate buffer (WAR safe: readers synced at s-1)
        __syncthreads();
    }
#pragma unroll
    for (int mt = 0; mt < 4; mt++)
        wmma::store_matrix_sync(out + (size_t)(mt * 16) * ldo + n0 + w * 16,
                                acc[mt], ldo, wmma::mem_row_major);
}

// ---------------- K4: LSTM gates + h_new bf16 images ----------------
__global__ void gates(const float* __restrict__ c, const float* __restrict__ bl,
                      float* __restrict__ o_h, float* __restrict__ o_c) {
    int b = blockIdx.y;
    int u = blockIdx.x * 256 + threadIdx.x;
    float zi = bl[u], zf = bl[u + UN], zg = bl[u + 2 * UN], zo = bl[u + 3 * UN];
#pragma unroll
    for (int s = 0; s < ZSPLITS; s++) {
        const float* zp = g_zpart + (size_t)s * BB * NZ + (size_t)b * NZ;
        zi += zp[u]; zf += zp[u + UN]; zg += zp[u + 2 * UN]; zo += zp[u + 3 * UN];
    }
    float cn = sigf(zf) * c[b * UN + u] + sigf(zi) * tanhf(zg);
    float hn = sigf(zo) * tanhf(cn);
    o_c[b * UN + u] = cn;
    o_h[b * UN + u] = hn;
    split_write(g_xv_hi, g_xv_lo, (size_t)b * UN + u, hn);
}

// ---------------- K6: softmax over vocab (float4) ----------------
__global__ void softmax_k(const float* __restrict__ bv, float* __restrict__ o_y) {
    int b = blockIdx.x, tid = threadIdx.x;
    __shared__ float red[1024];
    const float4* lg4 = (const float4*)(g_logits + (size_t)b * VOC);
    const float4* bv4 = (const float4*)bv;
    float4* oy4 = (float4*)(o_y + (size_t)b * VOC);
    float mx = -1e30f;
    for (int n = tid; n < VOC / 4; n += 1024) {
        float4 l = lg4[n], v = bv4[n];
        mx = fmaxf(mx, fmaxf(fmaxf(l.x + v.x, l.y + v.y), fmaxf(l.z + v.z, l.w + v.w)));
    }
    red[tid] = mx; __syncthreads();
    for (int s = 512; s > 0; s >>= 1) {
        if (tid < s) red[tid] = fmaxf(red[tid], red[tid + s]);
        __syncthreads();
    }
    float M = red[0]; __syncthreads();
    float sum = 0.f;
    for (int n = tid; n < VOC / 4; n += 1024) {
        float4 l = lg4[n], v = bv4[n];
        float4 e = make_float4(__expf(l.x + v.x - M), __expf(l.y + v.y - M),
                               __expf(l.z + v.z - M), __expf(l.w + v.w - M));
        oy4[n] = e;
        sum += e.x + e.y + e.z + e.w;
    }
    red[tid] = sum; __syncthreads();
    for (int s = 512; s > 0; s >>= 1) {
        if (tid < s) red[tid] += red[tid + s];
        __syncthreads();
    }
    float inv = 1.0f / red[0];
    for (int n = tid; n < VOC / 4; n += 1024) {
        float4 e = oy4[n];
        e.x *= inv; e.y *= inv; e.z *= inv; e.w *= inv;
        oy4[n] = e;
    }
}

// ---------------- launch ----------------
extern "C" void kernel_launch(void* const* d_in, const int* in_sizes, int n_in,
                              void* d_out, int out_size) {
    (void)in_sizes; (void)n_in; (void)out_size;
    const int*   X   = (const int*)d_in[0];
    const float* a   = (const float*)d_in[1];
    const float* h   = (const float*)d_in[2];
    const float* c   = (const float*)d_in[3];
    const float* emb = (const float*)d_in[4];
    // d_in[5..10] dead (softmax over size-1 axis == 1)
    const float* Wx  = (const float*)d_in[11];
    const float* Wh  = (const float*)d_in[12];
    const float* bl  = (const float*)d_in[13];
    const float* Wv  = (const float*)d_in[14];
    const float* bv  = (const float*)d_in[15];

    float* out     = (float*)d_out;
    float* o_y     = out;
    float* o_ctx   = o_y + (size_t)BB * VOC;
    float* o_alpha = o_ctx + BB * AD;
    float* o_h     = o_alpha + BB * TXX;
    float* o_c     = o_h + BB * UN;

    static int cfg_done = 0;
    if (!cfg_done) {
        cudaFuncSetAttribute(wgemm, cudaFuncAttributeMaxDynamicSharedMemorySize, WG_SMEM);
        cfg_done = 1;
    }

    ctx_partial<<<dim3(8, 64), 256>>>(a);
    ctx_finalize<<<dim3(4, 64), 256>>>(X, emb, h, o_ctx, o_alpha);
    // z = xin@[Wx;Wh] : K=2560 = 4 splits x 10 stages of 64; 32 n-blocks of 128
    wgemm<<<dim3(NZ / 128, ZSPLITS), 256, WG_SMEM>>>(
        Wx, Wh, AD + ED, NZ, /*in_sel=*/0, KXIN, (KXIN / 64) / ZSPLITS, /*out_sel=*/0, NZ);
    gates<<<dim3(4, 64), 256>>>(c, bl, o_h, o_c);
    // logits = h_new@Wv : K=1024 = 16 stages of 64; 250 n-blocks of 128
    wgemm<<<dim3(VOC / 128, 1), 256, WG_SMEM>>>(
        Wv, Wv, 0x7fffffff, VOC, /*in_sel=*/1, UN, UN / 64, /*out_sel=*/1, VOC);
    softmax_k<<<64, 1024>>>(bv, o_y);
}

// round 9
// speedup vs baseline: 1.3999x; 1.3837x over previous
#include <cuda_runtime.h>
#include <cuda_bf16.h>
#include <cuda_fp16.h>
#include <mma.h>

using namespace nvcuda;

#define BB    64
#define TXX   1024
#define AD    1024
#define UN    1024
#define VOC   32000
#define ED    512
#define KXIN  2560
#define NZ    4096
#define ZSPLITS 4

#define TP 72         // smem tile pitch (elems): 64 + 8

// ---------------- scratch (__device__ globals; NEVER passed from host) ----------------
__device__ __align__(16) float g_pctx[8 * BB * AD];
__device__ __align__(16) __nv_bfloat16 g_xz_hi[BB * KXIN];
__device__ __align__(16) __nv_bfloat16 g_xz_lo[BB * KXIN];
__device__ __align__(16) half g_xv_h16[BB * UN];
__device__ __align__(16) float g_zpart[ZSPLITS * BB * NZ];
__device__ __align__(16) float g_logits[BB * VOC];

__device__ __forceinline__ float sigf(float x) { return 1.0f / (1.0f + __expf(-x)); }

__device__ __forceinline__ void split_write(__nv_bfloat16* hi, __nv_bfloat16* lo,
                                            size_t idx, float v) {
    __nv_bfloat16 h = __float2bfloat16(v);
    hi[idx] = h;
    lo[idx] = __float2bfloat16(v - __bfloat162float(h));
}

// ---------------- K1: context partial sums ----------------
__global__ void ctx_partial(const float* __restrict__ a) {
    int d4 = threadIdx.x;
    int b  = blockIdx.y;
    int t0 = blockIdx.x * 128;
    const float4* p = (const float4*)(a + ((size_t)b * TXX + t0) * AD) + d4;
    float4 s = make_float4(0.f, 0.f, 0.f, 0.f);
#pragma unroll 8
    for (int t = 0; t < 128; t++) {
        float4 v = p[(size_t)t * 256];
        s.x += v.x; s.y += v.y; s.z += v.z; s.w += v.w;
    }
    ((float4*)g_pctx)[((size_t)blockIdx.x * BB + b) * 256 + d4] = s;
}

// ---------------- K2: finalize ctx + build xin bf16 hi/lo images ----------------
__global__ void ctx_finalize(const int* __restrict__ X, const float* __restrict__ emb,
                             const float* __restrict__ h,
                             float* __restrict__ o_ctx, float* __restrict__ o_alpha) {
    int b = blockIdx.y;
    int d = blockIdx.x * 256 + threadIdx.x;
    float s = 0.f;
#pragma unroll
    for (int j = 0; j < 8; j++) s += g_pctx[((size_t)j * BB + b) * AD + d];
    o_ctx[b * AD + d]    = s;
    o_alpha[b * TXX + d] = 1.0f;
    size_t row = (size_t)b * KXIN;
    split_write(g_xz_hi, g_xz_lo, row + d, s);
    if (d < ED) {
        int tok = X[b];
        split_write(g_xz_hi, g_xz_lo, row + AD + d, emb[(size_t)tok * ED + d]);
    }
    split_write(g_xz_hi, g_xz_lo, row + AD + ED + d, h[b * UN + d]);
}

// ---------------- zgemm: z = xin @ [Wx;Wh]  (bf16 hi/lo 3-term, R6 skeleton) ----------------
__global__ void __launch_bounds__(128, 4)
wgemm(const float* __restrict__ Wa, const float* __restrict__ Wb, int kbound, int ldw,
      int ldx, int nchunks, int ldo) {
    __shared__ __align__(32) __nv_bfloat16 sm[4 * 64 * TP];
    __nv_bfloat16* Ah = sm;
    __nv_bfloat16* Al = sm + 4608;
    __nv_bfloat16* Bh = sm + 9216;
    __nv_bfloat16* Bl = sm + 13824;

    const __nv_bfloat16* xhi = g_xz_hi;
    const __nv_bfloat16* xlo = g_xz_lo;

    int tid = threadIdx.x, w = tid >> 5;
    int n0 = blockIdx.x * 64;
    int k0 = blockIdx.y * nchunks * 64;
    float* out = g_zpart + (size_t)blockIdx.y * BB * NZ;

    wmma::fragment<wmma::accumulator, 16, 16, 16, float> acc[4];
#pragma unroll
    for (int i = 0; i < 4; i++) wmma::fill_fragment(acc[i], 0.0f);

    float4 pf[8];
    auto ldB = [&](int kg0) {
#pragma unroll
        for (int i = 0; i < 8; i++) {
            int idx = tid + i * 128;
            int k = idx >> 4, f4c = idx & 15;
            int kg = kg0 + k;
            const float* wrow = (kg < kbound) ? (Wa + (size_t)kg * ldw)
                                              : (Wb + (size_t)(kg - kbound) * ldw);
            pf[i] = __ldg((const float4*)(wrow + n0) + f4c);
        }
    };

    ldB(k0);
    for (int ci = 0; ci < nchunks; ci++) {
        int kg0 = k0 + ci * 64;
        __syncthreads();
#pragma unroll
        for (int i = 0; i < 4; i++) {
            int idx = tid + i * 128;
            int row = idx >> 3, j = idx & 7;
            size_t so = ((size_t)row * ldx + kg0) / 8 + j;
            ((uint4*)Ah)[row * 9 + j] = ((const uint4*)xhi)[so];
            ((uint4*)Al)[row * 9 + j] = ((const uint4*)xlo)[so];
        }
#pragma unroll
        for (int i = 0; i < 8; i++) {
            int idx = tid + i * 128;
            int k = idx >> 4, f4c = idx & 15;
            float4 v = pf[i];
            __nv_bfloat16 h0 = __float2bfloat16(v.x), h1 = __float2bfloat16(v.y);
            __nv_bfloat16 h2 = __float2bfloat16(v.z), h3 = __float2bfloat16(v.w);
            __nv_bfloat16 l0 = __float2bfloat16(v.x - __bfloat162float(h0));
            __nv_bfloat16 l1 = __float2bfloat16(v.y - __bfloat162float(h1));
            __nv_bfloat16 l2 = __float2bfloat16(v.z - __bfloat162float(h2));
            __nv_bfloat16 l3 = __float2bfloat16(v.w - __bfloat162float(h3));
            int bo = k * TP + f4c * 4;
            *(__nv_bfloat162*)(Bh + bo)     = __halves2bfloat162(h0, h1);
            *(__nv_bfloat162*)(Bh + bo + 2) = __halves2bfloat162(h2, h3);
            *(__nv_bfloat162*)(Bl + bo)     = __halves2bfloat162(l0, l1);
            *(__nv_bfloat162*)(Bl + bo + 2) = __halves2bfloat162(l2, l3);
        }
        __syncthreads();
        if (ci + 1 < nchunks) ldB(kg0 + 64);
#pragma unroll
        for (int kt = 0; kt < 4; kt++) {
            wmma::fragment<wmma::matrix_b, 16, 16, 16, __nv_bfloat16, wmma::row_major> bh, bl;
            wmma::load_matrix_sync(bh, Bh + kt * 16 * TP + w * 16, TP);
            wmma::load_matrix_sync(bl, Bl + kt * 16 * TP + w * 16, TP);
            wmma::fragment<wmma::matrix_a, 16, 16, 16, __nv_bfloat16, wmma::row_major> af[4];
#pragma unroll
            for (int mt = 0; mt < 4; mt++)
                wmma::load_matrix_sync(af[mt], Ah + mt * 16 * TP + kt * 16, TP);
#pragma unroll
            for (int mt = 0; mt < 4; mt++) wmma::mma_sync(acc[mt], af[mt], bh, acc[mt]);
#pragma unroll
            for (int mt = 0; mt < 4; mt++) wmma::mma_sync(acc[mt], af[mt], bl, acc[mt]);
#pragma unroll
            for (int mt = 0; mt < 4; mt++)
                wmma::load_matrix_sync(af[mt], Al + mt * 16 * TP + kt * 16, TP);
#pragma unroll
            for (int mt = 0; mt < 4; mt++) wmma::mma_sync(acc[mt], af[mt], bh, acc[mt]);
        }
    }
#pragma unroll
    for (int mt = 0; mt < 4; mt++)
        wmma::store_matrix_sync(out + (size_t)(mt * 16) * ldo + n0 + w * 16,
                                acc[mt], ldo, wmma::mem_row_major);
}

// ---------------- vgemm16: logits = h_new @ Wv  (fp16 single-pass) ----------------
// 128 thr = 4 warps; tile 64m x 64n; K chunk 64; A+B reg-prefetched; 18432 B static smem
__global__ void __launch_bounds__(128, 4)
vgemm16(const float* __restrict__ Wv) {
    __shared__ __align__(32) half sm[2 * 64 * TP];
    half* Ah = sm;
    half* Bh = sm + 4608;

    int tid = threadIdx.x, w = tid >> 5;
    int n0 = blockIdx.x * 64;

    wmma::fragment<wmma::accumulator, 16, 16, 16, float> acc[4];
#pragma unroll
    for (int i = 0; i < 4; i++) wmma::fill_fragment(acc[i], 0.0f);

    uint4  pa[4];
    float4 pb[8];
    auto ldAB = [&](int kg0) {
        // A: 64 rows x 64 k fp16 = 512 uint4; 128 thr -> 4 each
#pragma unroll
        for (int i = 0; i < 4; i++) {
            int idx = tid + i * 128;
            int row = idx >> 3, j = idx & 7;
            pa[i] = ((const uint4*)g_xv_h16)[(size_t)row * (UN / 8) + kg0 / 8 + j];
        }
        // B: 64 k x 64 n fp32 = 1024 float4; 8 each
#pragma unroll
        for (int i = 0; i < 8; i++) {
            int idx = tid + i * 128;
            int k = idx >> 4, f4c = idx & 15;
            pb[i] = __ldg((const float4*)(Wv + (size_t)(kg0 + k) * VOC + n0) + f4c);
        }
    };

    ldAB(0);
    for (int ci = 0; ci < UN / 64; ci++) {
        __syncthreads();
#pragma unroll
        for (int i = 0; i < 4; i++) {
            int idx = tid + i * 128;
            int row = idx >> 3, j = idx & 7;
            ((uint4*)Ah)[row * 9 + j] = pa[i];
        }
#pragma unroll
        for (int i = 0; i < 8; i++) {
            int idx = tid + i * 128;
            int k = idx >> 4, f4c = idx & 15;
            float4 v = pb[i];
            half2 h01 = __floats2half2_rn(v.x, v.y);
            half2 h23 = __floats2half2_rn(v.z, v.w);
            int bo = k * TP + f4c * 4;
            *(half2*)(Bh + bo)     = h01;
            *(half2*)(Bh + bo + 2) = h23;
        }
        __syncthreads();
        if (ci + 1 < UN / 64) ldAB((ci + 1) * 64);   // LDGs fly under the mma
#pragma unroll
        for (int kt = 0; kt < 4; kt++) {
            wmma::fragment<wmma::matrix_b, 16, 16, 16, half, wmma::row_major> bf;
            wmma::load_matrix_sync(bf, Bh + kt * 16 * TP + w * 16, TP);
            wmma::fragment<wmma::matrix_a, 16, 16, 16, half, wmma::row_major> af[4];
#pragma unroll
            for (int mt = 0; mt < 4; mt++)
                wmma::load_matrix_sync(af[mt], Ah + mt * 16 * TP + kt * 16, TP);
#pragma unroll
            for (int mt = 0; mt < 4; mt++) wmma::mma_sync(acc[mt], af[mt], bf, acc[mt]);
        }
    }
#pragma unroll
    for (int mt = 0; mt < 4; mt++)
        wmma::store_matrix_sync(g_logits + (size_t)(mt * 16) * VOC + n0 + w * 16,
                                acc[mt], VOC, wmma::mem_row_major);
}

// ---------------- K4: LSTM gates + h_new fp16 image ----------------
__global__ void gates(const float* __restrict__ c, const float* __restrict__ bl,
                      float* __restrict__ o_h, float* __restrict__ o_c) {
    int b = blockIdx.y;
    int u = blockIdx.x * 256 + threadIdx.x;
    float zi = bl[u], zf = bl[u + UN], zg = bl[u + 2 * UN], zo = bl[u + 3 * UN];
#pragma unroll
    for (int s = 0; s < ZSPLITS; s++) {
        const float* zp = g_zpart + (size_t)s * BB * NZ + (size_t)b * NZ;
        zi += zp[u]; zf += zp[u + UN]; zg += zp[u + 2 * UN]; zo += zp[u + 3 * UN];
    }
    float cn = sigf(zf) * c[b * UN + u] + sigf(zi) * tanhf(zg);
    float hn = sigf(zo) * tanhf(cn);
    o_c[b * UN + u] = cn;
    o_h[b * UN + u] = hn;
    g_xv_h16[(size_t)b * UN + u] = __float2half_rn(hn);
}

// ---------------- K6: softmax over vocab (float4) ----------------
__global__ void softmax_k(const float* __restrict__ bv, float* __restrict__ o_y) {
    int b = blockIdx.x, tid = threadIdx.x;
    __shared__ float red[1024];
    const float4* lg4 = (const float4*)(g_logits + (size_t)b * VOC);
    const float4* bv4 = (const float4*)bv;
    float4* oy4 = (float4*)(o_y + (size_t)b * VOC);
    float mx = -1e30f;
    for (int n = tid; n < VOC / 4; n += 1024) {
        float4 l = lg4[n], v = bv4[n];
        mx = fmaxf(mx, fmaxf(fmaxf(l.x + v.x, l.y + v.y), fmaxf(l.z + v.z, l.w + v.w)));
    }
    red[tid] = mx; __syncthreads();
    for (int s = 512; s > 0; s >>= 1) {
        if (tid < s) red[tid] = fmaxf(red[tid], red[tid + s]);
        __syncthreads();
    }
    float M = red[0]; __syncthreads();
    float sum = 0.f;
    for (int n = tid; n < VOC / 4; n += 1024) {
        float4 l = lg4[n], v = bv4[n];
        float4 e = make_float4(__expf(l.x + v.x - M), __expf(l.y + v.y - M),
                               __expf(l.z + v.z - M), __expf(l.w + v.w - M));
        oy4[n] = e;
        sum += e.x + e.y + e.z + e.w;
    }
    red[tid] = sum; __syncthreads();
    for (int s = 512; s > 0; s >>= 1) {
        if (tid < s) red[tid] += red[tid + s];
        __syncthreads();
    }
    float inv = 1.0f / red[0];
    for (int n = tid; n < VOC / 4; n += 1024) {
        float4 e = oy4[n];
        e.x *= inv; e.y *= inv; e.z *= inv; e.w *= inv;
        oy4[n] = e;
    }
}

// ---------------- launch ----------------
extern "C" void kernel_launch(void* const* d_in, const int* in_sizes, int n_in,
                              void* d_out, int out_size) {
    (void)in_sizes; (void)n_in; (void)out_size;
    const int*   X   = (const int*)d_in[0];
    const float* a   = (const float*)d_in[1];
    const float* h   = (const float*)d_in[2];
    const float* c   = (const float*)d_in[3];
    const float* emb = (const float*)d_in[4];
    // d_in[5..10] dead (softmax over size-1 axis == 1)
    const float* Wx  = (const float*)d_in[11];
    const float* Wh  = (const float*)d_in[12];
    const float* bl  = (const float*)d_in[13];
    const float* Wv  = (const float*)d_in[14];
    const float* bv  = (const float*)d_in[15];

    float* out     = (float*)d_out;
    float* o_y     = out;
    float* o_ctx   = o_y + (size_t)BB * VOC;
    float* o_alpha = o_ctx + BB * AD;
    float* o_h     = o_alpha + BB * TXX;
    float* o_c     = o_h + BB * UN;

    ctx_partial<<<dim3(8, 64), 256>>>(a);
    ctx_finalize<<<dim3(4, 64), 256>>>(X, emb, h, o_ctx, o_alpha);
    // z = xin@[Wx;Wh] : K=2560 = 4 splits x 10 chunks of 64; 64 n-blocks
    wgemm<<<dim3(NZ / 64, ZSPLITS), 128>>>(
        Wx, Wh, AD + ED, NZ, KXIN, (KXIN / 64) / ZSPLITS, NZ);
    gates<<<dim3(4, 64), 256>>>(c, bl, o_h, o_c);
    // logits = h_new@Wv : fp16 single-pass, 500 n-blocks
    vgemm16<<<dim3(VOC / 64, 1), 128>>>(Wv);
    softmax_k<<<64, 1024>>>(bv, o_y);
}

// round 10
// speedup vs baseline: 1.4861x; 1.0616x over previous
#include <cuda_runtime.h>
#include <cuda_bf16.h>
#include <cuda_fp16.h>
#include <mma.h>

using namespace nvcuda;

#define BB    64
#define TXX   1024
#define AD    1024
#define UN    1024
#define VOC   32000
#define ED    512
#define KXIN  2560
#define NZ    4096
#define ZSPLITS 8
#define TCH   16      // ctx t-chunks

#define TP 72         // smem tile pitch (elems): 64 + 8

// ---------------- scratch (__device__ globals; NEVER passed from host) ----------------
__device__ __align__(16) float g_pctx[TCH * BB * AD];
__device__ __align__(16) __nv_bfloat16 g_xz_hi[BB * KXIN];
__device__ __align__(16) __nv_bfloat16 g_xz_lo[BB * KXIN];
__device__ __align__(16) half g_xv_h16[BB * UN];
__device__ __align__(16) float g_zpart[ZSPLITS * BB * NZ];
__device__ __align__(16) float g_logits[BB * VOC];

__device__ __forceinline__ float sigf(float x) { return 1.0f / (1.0f + __expf(-x)); }

__device__ __forceinline__ void split_write(__nv_bfloat16* hi, __nv_bfloat16* lo,
                                            size_t idx, float v) {
    __nv_bfloat16 h = __float2bfloat16(v);
    hi[idx] = h;
    lo[idx] = __float2bfloat16(v - __bfloat162float(h));
}

// ---------------- K1: context partial sums ----------------
// grid (16 t-chunks, 64 b), block 256; each block sums 64 t-rows
__global__ void ctx_partial(const float* __restrict__ a) {
    int d4 = threadIdx.x;
    int b  = blockIdx.y;
    int t0 = blockIdx.x * 64;
    const float4* p = (const float4*)(a + ((size_t)b * TXX + t0) * AD) + d4;
    float4 s = make_float4(0.f, 0.f, 0.f, 0.f);
#pragma unroll 8
    for (int t = 0; t < 64; t++) {
        float4 v = p[(size_t)t * 256];
        s.x += v.x; s.y += v.y; s.z += v.z; s.w += v.w;
    }
    ((float4*)g_pctx)[((size_t)blockIdx.x * BB + b) * 256 + d4] = s;
}

// ---------------- K2: finalize ctx + build xin bf16 hi/lo images ----------------
__global__ void ctx_finalize(const int* __restrict__ X, const float* __restrict__ emb,
                             const float* __restrict__ h,
                             float* __restrict__ o_ctx, float* __restrict__ o_alpha) {
    int b = blockIdx.y;
    int d = blockIdx.x * 256 + threadIdx.x;
    float s = 0.f;
#pragma unroll
    for (int j = 0; j < TCH; j++) s += g_pctx[((size_t)j * BB + b) * AD + d];
    o_ctx[b * AD + d]    = s;
    o_alpha[b * TXX + d] = 1.0f;
    size_t row = (size_t)b * KXIN;
    split_write(g_xz_hi, g_xz_lo, row + d, s);
    if (d < ED) {
        int tok = X[b];
        split_write(g_xz_hi, g_xz_lo, row + AD + d, emb[(size_t)tok * ED + d]);
    }
    split_write(g_xz_hi, g_xz_lo, row + AD + ED + d, h[b * UN + d]);
}

// ---------------- zgemm: z = xin @ [Wx;Wh]  (bf16 hi/lo 3-term) ----------------
__global__ void __launch_bounds__(128, 4)
wgemm(const float* __restrict__ Wa, const float* __restrict__ Wb, int kbound, int ldw,
      int ldx, int nchunks, int ldo) {
    __shared__ __align__(32) __nv_bfloat16 sm[4 * 64 * TP];
    __nv_bfloat16* Ah = sm;
    __nv_bfloat16* Al = sm + 4608;
    __nv_bfloat16* Bh = sm + 9216;
    __nv_bfloat16* Bl = sm + 13824;

    const __nv_bfloat16* xhi = g_xz_hi;
    const __nv_bfloat16* xlo = g_xz_lo;

    int tid = threadIdx.x, w = tid >> 5;
    int n0 = blockIdx.x * 64;
    int k0 = blockIdx.y * nchunks * 64;
    float* out = g_zpart + (size_t)blockIdx.y * BB * NZ;

    wmma::fragment<wmma::accumulator, 16, 16, 16, float> acc[4];
#pragma unroll
    for (int i = 0; i < 4; i++) wmma::fill_fragment(acc[i], 0.0f);

    float4 pf[8];
    auto ldB = [&](int kg0) {
#pragma unroll
        for (int i = 0; i < 8; i++) {
            int idx = tid + i * 128;
            int k = idx >> 4, f4c = idx & 15;
            int kg = kg0 + k;
            const float* wrow = (kg < kbound) ? (Wa + (size_t)kg * ldw)
                                              : (Wb + (size_t)(kg - kbound) * ldw);
            pf[i] = __ldg((const float4*)(wrow + n0) + f4c);
        }
    };

    ldB(k0);
    for (int ci = 0; ci < nchunks; ci++) {
        int kg0 = k0 + ci * 64;
        __syncthreads();
#pragma unroll
        for (int i = 0; i < 4; i++) {
            int idx = tid + i * 128;
            int row = idx >> 3, j = idx & 7;
            size_t so = ((size_t)row * ldx + kg0) / 8 + j;
            ((uint4*)Ah)[row * 9 + j] = ((const uint4*)xhi)[so];
            ((uint4*)Al)[row * 9 + j] = ((const uint4*)xlo)[so];
        }
#pragma unroll
        for (int i = 0; i < 8; i++) {
            int idx = tid + i * 128;
            int k = idx >> 4, f4c = idx & 15;
            float4 v = pf[i];
            __nv_bfloat16 h0 = __float2bfloat16(v.x), h1 = __float2bfloat16(v.y);
            __nv_bfloat16 h2 = __float2bfloat16(v.z), h3 = __float2bfloat16(v.w);
            __nv_bfloat16 l0 = __float2bfloat16(v.x - __bfloat162float(h0));
            __nv_bfloat16 l1 = __float2bfloat16(v.y - __bfloat162float(h1));
            __nv_bfloat16 l2 = __float2bfloat16(v.z - __bfloat162float(h2));
            __nv_bfloat16 l3 = __float2bfloat16(v.w - __bfloat162float(h3));
            int bo = k * TP + f4c * 4;
            *(__nv_bfloat162*)(Bh + bo)     = __halves2bfloat162(h0, h1);
            *(__nv_bfloat162*)(Bh + bo + 2) = __halves2bfloat162(h2, h3);
            *(__nv_bfloat162*)(Bl + bo)     = __halves2bfloat162(l0, l1);
            *(__nv_bfloat162*)(Bl + bo + 2) = __halves2bfloat162(l2, l3);
        }
        __syncthreads();
        if (ci + 1 < nchunks) ldB(kg0 + 64);
#pragma unroll
        for (int kt = 0; kt < 4; kt++) {
            wmma::fragment<wmma::matrix_b, 16, 16, 16, __nv_bfloat16, wmma::row_major> bh, bl;
            wmma::load_matrix_sync(bh, Bh + kt * 16 * TP + w * 16, TP);
            wmma::load_matrix_sync(bl, Bl + kt * 16 * TP + w * 16, TP);
            wmma::fragment<wmma::matrix_a, 16, 16, 16, __nv_bfloat16, wmma::row_major> af[4];
#pragma unroll
            for (int mt = 0; mt < 4; mt++)
                wmma::load_matrix_sync(af[mt], Ah + mt * 16 * TP + kt * 16, TP);
#pragma unroll
            for (int mt = 0; mt < 4; mt++) wmma::mma_sync(acc[mt], af[mt], bh, acc[mt]);
#pragma unroll
            for (int mt = 0; mt < 4; mt++) wmma::mma_sync(acc[mt], af[mt], bl, acc[mt]);
#pragma unroll
            for (int mt = 0; mt < 4; mt++)
                wmma::load_matrix_sync(af[mt], Al + mt * 16 * TP + kt * 16, TP);
#pragma unroll
            for (int mt = 0; mt < 4; mt++) wmma::mma_sync(acc[mt], af[mt], bh, acc[mt]);
        }
    }
#pragma unroll
    for (int mt = 0; mt < 4; mt++)
        wmma::store_matrix_sync(out + (size_t)(mt * 16) * ldo + n0 + w * 16,
                                acc[mt], ldo, wmma::mem_row_major);
}

// ---------------- vgemm16: logits = h_new @ Wv  (fp16 single-pass) ----------------
__global__ void __launch_bounds__(128, 4)
vgemm16(const float* __restrict__ Wv) {
    __shared__ __align__(32) half sm[2 * 64 * TP];
    half* Ah = sm;
    half* Bh = sm + 4608;

    int tid = threadIdx.x, w = tid >> 5;
    int n0 = blockIdx.x * 64;

    wmma::fragment<wmma::accumulator, 16, 16, 16, float> acc[4];
#pragma unroll
    for (int i = 0; i < 4; i++) wmma::fill_fragment(acc[i], 0.0f);

    uint4  pa[4];
    float4 pb[8];
    auto ldAB = [&](int kg0) {
#pragma unroll
        for (int i = 0; i < 4; i++) {
            int idx = tid + i * 128;
            int row = idx >> 3, j = idx & 7;
            pa[i] = ((const uint4*)g_xv_h16)[(size_t)row * (UN / 8) + kg0 / 8 + j];
        }
#pragma unroll
        for (int i = 0; i < 8; i++) {
            int idx = tid + i * 128;
            int k = idx >> 4, f4c = idx & 15;
            pb[i] = __ldg((const float4*)(Wv + (size_t)(kg0 + k) * VOC + n0) + f4c);
        }
    };

    ldAB(0);
    for (int ci = 0; ci < UN / 64; ci++) {
        __syncthreads();
#pragma unroll
        for (int i = 0; i < 4; i++) {
            int idx = tid + i * 128;
            int row = idx >> 3, j = idx & 7;
            ((uint4*)Ah)[row * 9 + j] = pa[i];
        }
#pragma unroll
        for (int i = 0; i < 8; i++) {
            int idx = tid + i * 128;
            int k = idx >> 4, f4c = idx & 15;
            float4 v = pb[i];
            half2 h01 = __floats2half2_rn(v.x, v.y);
            half2 h23 = __floats2half2_rn(v.z, v.w);
            int bo = k * TP + f4c * 4;
            *(half2*)(Bh + bo)     = h01;
            *(half2*)(Bh + bo + 2) = h23;
        }
        __syncthreads();
        if (ci + 1 < UN / 64) ldAB((ci + 1) * 64);
#pragma unroll
        for (int kt = 0; kt < 4; kt++) {
            wmma::fragment<wmma::matrix_b, 16, 16, 16, half, wmma::row_major> bf;
            wmma::load_matrix_sync(bf, Bh + kt * 16 * TP + w * 16, TP);
            wmma::fragment<wmma::matrix_a, 16, 16, 16, half, wmma::row_major> af[4];
#pragma unroll
            for (int mt = 0; mt < 4; mt++)
                wmma::load_matrix_sync(af[mt], Ah + mt * 16 * TP + kt * 16, TP);
#pragma unroll
            for (int mt = 0; mt < 4; mt++) wmma::mma_sync(acc[mt], af[mt], bf, acc[mt]);
        }
    }
#pragma unroll
    for (int mt = 0; mt < 4; mt++)
        wmma::store_matrix_sync(g_logits + (size_t)(mt * 16) * VOC + n0 + w * 16,
                                acc[mt], VOC, wmma::mem_row_major);
}

// ---------------- K4: LSTM gates + h_new fp16 image ----------------
__global__ void gates(const float* __restrict__ c, const float* __restrict__ bl,
                      float* __restrict__ o_h, float* __restrict__ o_c) {
    int b = blockIdx.y;
    int u = blockIdx.x * 256 + threadIdx.x;
    float zi = bl[u], zf = bl[u + UN], zg = bl[u + 2 * UN], zo = bl[u + 3 * UN];
#pragma unroll
    for (int s = 0; s < ZSPLITS; s++) {
        const float* zp = g_zpart + (size_t)s * BB * NZ + (size_t)b * NZ;
        zi += zp[u]; zf += zp[u + UN]; zg += zp[u + 2 * UN]; zo += zp[u + 3 * UN];
    }
    float cn = sigf(zf) * c[b * UN + u] + sigf(zi) * tanhf(zg);
    float hn = sigf(zo) * tanhf(cn);
    o_c[b * UN + u] = cn;
    o_h[b * UN + u] = hn;
    g_xv_h16[(size_t)b * UN + u] = __float2half_rn(hn);
}

// ---------------- K6: softmax over vocab (float4) ----------------
__global__ void softmax_k(const float* __restrict__ bv, float* __restrict__ o_y) {
    int b = blockIdx.x, tid = threadIdx.x;
    __shared__ float red[1024];
    const float4* lg4 = (const float4*)(g_logits + (size_t)b * VOC);
    const float4* bv4 = (const float4*)bv;
    float4* oy4 = (float4*)(o_y + (size_t)b * VOC);
    float mx = -1e30f;
    for (int n = tid; n < VOC / 4; n += 1024) {
        float4 l = lg4[n], v = bv4[n];
        mx = fmaxf(mx, fmaxf(fmaxf(l.x + v.x, l.y + v.y), fmaxf(l.z + v.z, l.w + v.w)));
    }
    red[tid] = mx; __syncthreads();
    for (int s = 512; s > 0; s >>= 1) {
        if (tid < s) red[tid] = fmaxf(red[tid], red[tid + s]);
        __syncthreads();
    }
    float M = red[0]; __syncthreads();
    float sum = 0.f;
    for (int n = tid; n < VOC / 4; n += 1024) {
        float4 l = lg4[n], v = bv4[n];
        float4 e = make_float4(__expf(l.x + v.x - M), __expf(l.y + v.y - M),
                               __expf(l.z + v.z - M), __expf(l.w + v.w - M));
        oy4[n] = e;
        sum += e.x + e.y + e.z + e.w;
    }
    red[tid] = sum; __syncthreads();
    for (int s = 512; s > 0; s >>= 1) {
        if (tid < s) red[tid] += red[tid + s];
        __syncthreads();
    }
    float inv = 1.0f / red[0];
    for (int n = tid; n < VOC / 4; n += 1024) {
        float4 e = oy4[n];
        e.x *= inv; e.y *= inv; e.z *= inv; e.w *= inv;
        oy4[n] = e;
    }
}

// ---------------- launch ----------------
extern "C" void kernel_launch(void* const* d_in, const int* in_sizes, int n_in,
                              void* d_out, int out_size) {
    (void)in_sizes; (void)n_in; (void)out_size;
    const int*   X   = (const int*)d_in[0];
    const float* a   = (const float*)d_in[1];
    const float* h   = (const float*)d_in[2];
    const float* c   = (const float*)d_in[3];
    const float* emb = (const float*)d_in[4];
    // d_in[5..10] dead (softmax over size-1 axis == 1)
    const float* Wx  = (const float*)d_in[11];
    const float* Wh  = (const float*)d_in[12];
    const float* bl  = (const float*)d_in[13];
    const float* Wv  = (const float*)d_in[14];
    const float* bv  = (const float*)d_in[15];

    float* out     = (float*)d_out;
    float* o_y     = out;
    float* o_ctx   = o_y + (size_t)BB * VOC;
    float* o_alpha = o_ctx + BB * AD;
    float* o_h     = o_alpha + BB * TXX;
    float* o_c     = o_h + BB * UN;

    ctx_partial<<<dim3(TCH, 64), 256>>>(a);
    ctx_finalize<<<dim3(4, 64), 256>>>(X, emb, h, o_ctx, o_alpha);
    // z = xin@[Wx;Wh] : K=2560 = 8 splits x 5 chunks of 64; 64 n-blocks -> 512 blocks
    wgemm<<<dim3(NZ / 64, ZSPLITS), 128>>>(
        Wx, Wh, AD + ED, NZ, KXIN, (KXIN / 64) / ZSPLITS, NZ);
    gates<<<dim3(4, 64), 256>>>(c, bl, o_h, o_c);
    // logits = h_new@Wv : fp16 single-pass, 500 n-blocks
    vgemm16<<<dim3(VOC / 64, 1), 128>>>(Wv);
    softmax_k<<<64, 1024>>>(bv, o_y);
}